// round 1
// baseline (speedup 1.0000x reference)
#include <cuda_runtime.h>

// Shapes are fixed by the problem: x[8,1024,1024], w_qkv[1024,3072],
// w_proj[1024,1024], b_proj[1024]. Outputs concatenated in d_out:
// out[8,1024,1024] then attn[8,16,1024,1024] (reference returns (out, attn)).
#define B_   8
#define N_   1024
#define C_   1024
#define H_   16
#define D_   64
#define M_   (B_ * N_)      // 8192 rows
#define QKVC (3 * C_)       // 3072
#define ROWS 32             // attention row-slab per block

// Allocation-free scratch (device globals, ~134 MB total)
__device__ float g_q[(size_t)B_ * H_ * N_ * D_];
__device__ float g_k[(size_t)B_ * H_ * N_ * D_];
__device__ float g_v[(size_t)B_ * H_ * N_ * D_];
__device__ float g_ctx[(size_t)M_ * C_];

// ---------------------------------------------------------------------------
// Tiled SGEMM: C[M,Ncols] = A[M,K] @ B[K,Ncols]
// 128x128 tile, BK=16, 256 threads, 8x8 per thread (2x2 blocked fragments).
// MODE 0: A = x, B = w_qkv, epilogue scatters into g_q/g_k/g_v (head-major).
// MODE 1: A = g_ctx, B = w_proj, epilogue adds bias, writes to out.
// ---------------------------------------------------------------------------
template <int MODE>
__global__ void __launch_bounds__(256) sgemm_kernel(
    const float* __restrict__ A_in, const float* __restrict__ Bm,
    const float* __restrict__ bias, float* __restrict__ out,
    int K, int Ncols)
{
    const float* A = (MODE == 1) ? g_ctx : A_in;

    __shared__ float As[16][128];   // transposed A tile: As[k][m]
    __shared__ float Bs[16][128];   // Bs[k][n]

    const int tid = threadIdx.x;
    const int tx  = tid & 15;       // 0..15
    const int ty  = tid >> 4;       // 0..15
    const int bm0 = blockIdx.y * 128;
    const int bn0 = blockIdx.x * 128;

    const int r0 = ty * 4, r1 = 64 + ty * 4;
    const int c0 = tx * 4, c1 = 64 + tx * 4;

    float acc[8][8];
    #pragma unroll
    for (int i = 0; i < 8; i++)
        #pragma unroll
        for (int j = 0; j < 8; j++) acc[i][j] = 0.0f;

    for (int k0 = 0; k0 < K; k0 += 16) {
        // A tile 128x16 -> As transposed
        #pragma unroll
        for (int l = 0; l < 2; l++) {
            int idx = tid * 2 + l;            // 0..511
            int r   = idx >> 2;               // 0..127
            int c4  = idx & 3;                // 0..3
            float4 a = *(const float4*)&A[(size_t)(bm0 + r) * K + k0 + c4 * 4];
            As[c4 * 4 + 0][r] = a.x;
            As[c4 * 4 + 1][r] = a.y;
            As[c4 * 4 + 2][r] = a.z;
            As[c4 * 4 + 3][r] = a.w;
        }
        // B tile 16x128
        #pragma unroll
        for (int l = 0; l < 2; l++) {
            int idx = tid * 2 + l;            // 0..511
            int r   = idx >> 5;               // 0..15
            int c4  = idx & 31;               // 0..31
            *(float4*)&Bs[r][c4 * 4] =
                *(const float4*)&Bm[(size_t)(k0 + r) * Ncols + bn0 + c4 * 4];
        }
        __syncthreads();

        #pragma unroll
        for (int k = 0; k < 16; k++) {
            float ra[8], rb[8];
            *(float4*)&ra[0] = *(const float4*)&As[k][r0];
            *(float4*)&ra[4] = *(const float4*)&As[k][r1];
            *(float4*)&rb[0] = *(const float4*)&Bs[k][c0];
            *(float4*)&rb[4] = *(const float4*)&Bs[k][c1];
            #pragma unroll
            for (int i = 0; i < 8; i++)
                #pragma unroll
                for (int j = 0; j < 8; j++)
                    acc[i][j] += ra[i] * rb[j];
        }
        __syncthreads();
    }

    // epilogue
    #pragma unroll
    for (int i = 0; i < 8; i++) {
        int rr = bm0 + ((i < 4) ? (r0 + i) : (r1 + i - 4));
        #pragma unroll
        for (int j = 0; j < 8; j++) {
            int cc = bn0 + ((j < 4) ? (c0 + j) : (c1 + j - 4));
            float v = acc[i][j];
            if (MODE == 0) {
                int which = cc >> 10;      // 0=q,1=k,2=v
                int c     = cc & 1023;
                int h     = c >> 6;
                int d     = c & 63;
                int b     = rr >> 10;
                int n     = rr & 1023;
                size_t off = (((size_t)(b * H_ + h)) * N_ + n) * D_ + d;
                if (which == 0)      g_q[off] = v;
                else if (which == 1) g_k[off] = v;
                else                 g_v[off] = v;
            } else {
                out[(size_t)rr * Ncols + cc] = v + bias[cc];
            }
        }
    }
}

// ---------------------------------------------------------------------------
// Fused attention: per block = one (b,h) and a 32-row slab of queries.
// Phase A: S[32,1024] = Q @ K^T * scale  (K chunked 128 rows at a time)
// Phase B: row softmax, write attn to gmem, keep probs in smem
// Phase C: ctx[32,64] = S @ V  (V chunked 128 rows), write to g_ctx [B,N,C]
// Dynamic smem: S (128KB) + Qs (8.25KB) + shared K/V chunk buffer (32KB)
// ---------------------------------------------------------------------------
__global__ void __launch_bounds__(256) attn_kernel(float* __restrict__ attn_out)
{
    extern __shared__ float sm[];
    float* S   = sm;                          // ROWS * N_ = 32768 floats
    float* Qs  = sm + ROWS * N_;              // 64 * 33   = 2112 floats (transposed, padded)
    float* KVs = Qs + 64 * 33;                // 8192 floats (Kst or Vs)

    const int tid  = threadIdx.x;
    const int lane = tid & 31;
    const int w    = tid >> 5;                // warp 0..7

    const int nrb    = N_ / ROWS;             // 32 row-blocks per (b,h)
    const int rowblk = blockIdx.x % nrb;
    const int bh     = blockIdx.x / nrb;      // 0..127
    const int row0   = rowblk * ROWS;
    const int h      = bh & (H_ - 1);
    const int b      = bh / H_;

    const float* Qg = g_q + (size_t)bh * N_ * D_ + (size_t)row0 * D_;
    const float* Kg = g_k + (size_t)bh * N_ * D_;
    const float* Vg = g_v + (size_t)bh * N_ * D_;

    // Load Q slab (32x64) transposed: Qs[d*33 + r]
    #pragma unroll
    for (int l = 0; l < 2; l++) {
        int idx = tid * 2 + l;                // 0..511
        int r   = idx >> 4;                   // 0..31
        int c4  = idx & 15;                   // 0..15
        float4 qv = *(const float4*)&Qg[r * D_ + c4 * 4];
        Qs[(c4 * 4 + 0) * 33 + r] = qv.x;
        Qs[(c4 * 4 + 1) * 33 + r] = qv.y;
        Qs[(c4 * 4 + 2) * 33 + r] = qv.z;
        Qs[(c4 * 4 + 3) * 33 + r] = qv.w;
    }

    const int   rbase = w * 4;                // this warp's 4 query rows
    const float scale = 0.125f;               // 1/sqrt(64)

    // ---- Phase A: scores ----
    for (int m0 = 0; m0 < N_; m0 += 128) {
        // K chunk (128x64) transposed: KVs[d*128 + m']
        #pragma unroll
        for (int l = 0; l < 8; l++) {
            int idx = tid + 256 * l;          // 0..2047
            int r   = idx >> 4;               // 0..127
            int c4  = idx & 15;
            float4 kv = *(const float4*)&Kg[(size_t)(m0 + r) * D_ + c4 * 4];
            KVs[(c4 * 4 + 0) * 128 + r] = kv.x;
            KVs[(c4 * 4 + 1) * 128 + r] = kv.y;
            KVs[(c4 * 4 + 2) * 128 + r] = kv.z;
            KVs[(c4 * 4 + 3) * 128 + r] = kv.w;
        }
        __syncthreads();

        float acc[4][4];
        #pragma unroll
        for (int i = 0; i < 4; i++)
            #pragma unroll
            for (int j = 0; j < 4; j++) acc[i][j] = 0.0f;

        #pragma unroll 16
        for (int d = 0; d < D_; d++) {
            float4 kv = *(const float4*)&KVs[d * 128 + lane * 4];
            float q0 = Qs[d * 33 + rbase + 0];
            float q1 = Qs[d * 33 + rbase + 1];
            float q2 = Qs[d * 33 + rbase + 2];
            float q3 = Qs[d * 33 + rbase + 3];
            acc[0][0] += q0 * kv.x; acc[0][1] += q0 * kv.y; acc[0][2] += q0 * kv.z; acc[0][3] += q0 * kv.w;
            acc[1][0] += q1 * kv.x; acc[1][1] += q1 * kv.y; acc[1][2] += q1 * kv.z; acc[1][3] += q1 * kv.w;
            acc[2][0] += q2 * kv.x; acc[2][1] += q2 * kv.y; acc[2][2] += q2 * kv.z; acc[2][3] += q2 * kv.w;
            acc[3][0] += q3 * kv.x; acc[3][1] += q3 * kv.y; acc[3][2] += q3 * kv.z; acc[3][3] += q3 * kv.w;
        }
        #pragma unroll
        for (int i = 0; i < 4; i++) {
            float4 sv = make_float4(acc[i][0] * scale, acc[i][1] * scale,
                                    acc[i][2] * scale, acc[i][3] * scale);
            *(float4*)&S[(rbase + i) * N_ + m0 + lane * 4] = sv;
        }
        __syncthreads();
    }

    // ---- Phase B: softmax + write attn ----
    for (int r = w; r < ROWS; r += 8) {
        float* Srow = S + r * N_;
        float mx = -1e30f;
        for (int c = lane; c < N_; c += 32) mx = fmaxf(mx, Srow[c]);
        #pragma unroll
        for (int o = 16; o > 0; o >>= 1) mx = fmaxf(mx, __shfl_xor_sync(0xffffffffu, mx, o));
        float ssum = 0.0f;
        for (int c = lane; c < N_; c += 32) {
            float e = __expf(Srow[c] - mx);
            Srow[c] = e;
            ssum += e;
        }
        #pragma unroll
        for (int o = 16; o > 0; o >>= 1) ssum += __shfl_xor_sync(0xffffffffu, ssum, o);
        float inv = 1.0f / ssum;
        size_t abase = ((size_t)bh * N_ + row0 + r) * N_;
        for (int c = lane; c < N_; c += 32) {
            float p = Srow[c] * inv;
            Srow[c] = p;
            attn_out[abase + c] = p;
        }
    }
    __syncthreads();

    // ---- Phase C: ctx = S @ V ----
    float acc2[4][2];
    #pragma unroll
    for (int i = 0; i < 4; i++) { acc2[i][0] = 0.0f; acc2[i][1] = 0.0f; }
    const int cp = lane * 2;

    for (int m0 = 0; m0 < N_; m0 += 128) {
        // V chunk (128x64) natural layout: KVs[m'*64 + d]
        #pragma unroll
        for (int l = 0; l < 8; l++) {
            int idx = tid + 256 * l;
            int r   = idx >> 4;               // 0..127
            int c4  = idx & 15;
            *(float4*)&KVs[r * 64 + c4 * 4] =
                *(const float4*)&Vg[(size_t)(m0 + r) * D_ + c4 * 4];
        }
        __syncthreads();

        #pragma unroll 8
        for (int mm = 0; mm < 128; mm++) {
            float2 vv = *(const float2*)&KVs[mm * 64 + cp];
            float s0 = S[(rbase + 0) * N_ + m0 + mm];
            float s1 = S[(rbase + 1) * N_ + m0 + mm];
            float s2 = S[(rbase + 2) * N_ + m0 + mm];
            float s3 = S[(rbase + 3) * N_ + m0 + mm];
            acc2[0][0] += s0 * vv.x; acc2[0][1] += s0 * vv.y;
            acc2[1][0] += s1 * vv.x; acc2[1][1] += s1 * vv.y;
            acc2[2][0] += s2 * vv.x; acc2[2][1] += s2 * vv.y;
            acc2[3][0] += s3 * vv.x; acc2[3][1] += s3 * vv.y;
        }
        __syncthreads();
    }

    #pragma unroll
    for (int i = 0; i < 4; i++) {
        size_t m = (size_t)b * N_ + row0 + rbase + i;
        *(float2*)&g_ctx[m * C_ + h * D_ + cp] = make_float2(acc2[i][0], acc2[i][1]);
    }
}

// ---------------------------------------------------------------------------
extern "C" void kernel_launch(void* const* d_in, const int* in_sizes, int n_in,
                              void* d_out, int out_size)
{
    const float* x      = (const float*)d_in[0];
    const float* w_qkv  = (const float*)d_in[1];
    const float* w_proj = (const float*)d_in[2];
    const float* b_proj = (const float*)d_in[3];
    float* out  = (float*)d_out;
    float* attn = out + (size_t)M_ * C_;   // attn follows out in d_out

    dim3 thr(256);

    // 1) QKV GEMM with head-major scatter
    sgemm_kernel<0><<<dim3(QKVC / 128, M_ / 128), thr>>>(x, w_qkv, nullptr, nullptr, C_, QKVC);

    // 2) Fused scores -> softmax -> attn write -> AV
    int smem = (ROWS * N_ + 64 * 33 + 64 * 128) * (int)sizeof(float);  // 172288 B
    cudaFuncSetAttribute(attn_kernel, cudaFuncAttributeMaxDynamicSharedMemorySize, smem);
    attn_kernel<<<B_ * H_ * (N_ / ROWS), thr, smem>>>(attn);

    // 3) Projection GEMM + bias
    sgemm_kernel<1><<<dim3(C_ / 128, M_ / 128), thr>>>(nullptr, w_proj, b_proj, out, C_, C_);
}

// round 3
// speedup vs baseline: 2.4303x; 2.4303x over previous
#include <cuda_runtime.h>
#include <cuda_bf16.h>

typedef unsigned int u32;

#define B_   8
#define N_   1024
#define C_   1024
#define H_   16
#define D_   64
#define M_   (B_ * N_)     // 8192
#define QKVC 3072
#define BH_  (B_ * H_)     // 128

// ---------------- allocation-free scratch (device globals) ----------------
__device__ __align__(256) __nv_bfloat16 g_xh[(size_t)M_ * C_],  g_xl[(size_t)M_ * C_];
__device__ __align__(256) __nv_bfloat16 g_wqh[(size_t)QKVC * C_], g_wql[(size_t)QKVC * C_];
__device__ __align__(256) __nv_bfloat16 g_wph[(size_t)C_ * C_],  g_wpl[(size_t)C_ * C_];
__device__ __align__(256) __nv_bfloat16 g_qh[(size_t)BH_ * N_ * D_], g_ql[(size_t)BH_ * N_ * D_];
__device__ __align__(256) __nv_bfloat16 g_kh[(size_t)BH_ * N_ * D_], g_kl[(size_t)BH_ * N_ * D_];
__device__ __align__(256) __nv_bfloat16 g_vTh[(size_t)BH_ * D_ * N_], g_vTl[(size_t)BH_ * D_ * N_];
__device__ __align__(256) __nv_bfloat16 g_ah[(size_t)BH_ * N_ * N_], g_al[(size_t)BH_ * N_ * N_];
__device__ __align__(256) __nv_bfloat16 g_ch[(size_t)M_ * C_],  g_cl[(size_t)M_ * C_];

// ---------------- helpers ----------------
__device__ __forceinline__ u32 smem_u32(const void* p) {
    u32 a;
    asm("{ .reg .u64 t; cvta.to.shared.u64 t, %1; cvt.u32.u64 %0, t; }" : "=r"(a) : "l"(p));
    return a;
}
#define CP16(dst, src) \
    asm volatile("cp.async.cg.shared.global [%0], [%1], 16;" :: "r"(dst), "l"(src) : "memory")
#define CP_COMMIT() asm volatile("cp.async.commit_group;" ::: "memory")
#define CP_WAIT(n)  asm volatile("cp.async.wait_group %0;" :: "n"(n) : "memory")

__device__ __forceinline__ void mma16816(float* c, const u32* a, const u32* b) {
    asm volatile(
        "mma.sync.aligned.m16n8k16.row.col.f32.bf16.bf16.f32 "
        "{%0,%1,%2,%3}, {%4,%5,%6,%7}, {%8,%9}, {%0,%1,%2,%3};"
        : "+f"(c[0]), "+f"(c[1]), "+f"(c[2]), "+f"(c[3])
        : "r"(a[0]), "r"(a[1]), "r"(a[2]), "r"(a[3]), "r"(b[0]), "r"(b[1]));
}

__device__ __forceinline__ void splitf(float v, __nv_bfloat16& h, __nv_bfloat16& l) {
    h = __float2bfloat16(v);
    l = __float2bfloat16(v - __bfloat162float(h));
}

// ---------------------------------------------------------------------------
// Split-bf16 HMMA GEMM.  D[m][n] = sum_k A[m][k]*B[n][k]  (fp32 accum)
// Block tile 128 x NTILE, K-chunk 32, cp.async double buffer.
// Smem rows padded to 80B pitch (conflict-free fragment LDS).
// MODE 0: QKV  (x * wqkvT)      -> scatter q(scaled)/k/vT hi+lo
// MODE 1: S    (q * kT, per bh) -> fp32 scores into attn region
// MODE 2: AV   (attn * vT, bh)  -> ctx hi+lo (NTILE=64)
// MODE 3: OUT  (ctx * wprojT)   -> fp32 out + bias
// ---------------------------------------------------------------------------
template <int MODE>
__global__ void __launch_bounds__(256, 1) mma_gemm(float* __restrict__ out_f32,
                                                   const float* __restrict__ bias)
{
    constexpr int NTILE = (MODE == 2) ? 64 : 128;
    constexpr int KTOT  = (MODE == 1) ? 64 : 1024;
    constexpr int NC    = KTOT / 32;
    constexpr int MA    = (MODE == 2) ? 2 : 4;   // m-atoms (16 rows each) per warp
    constexpr int NA    = 4;                     // n-atoms (8 cols each) per warp
    constexpr int APART = 128 * 80;
    constexpr int BPART = NTILE * 80;
    constexpr int STAGE = 2 * APART + 2 * BPART;

    extern __shared__ char smem[];
    const u32 sb   = smem_u32(smem);
    const int tid  = threadIdx.x;
    const int wid  = tid >> 5, lane = tid & 31;
    const int g    = lane >> 2, t = lane & 3;
    const int bn   = blockIdx.x * NTILE;
    const int bm   = blockIdx.y * 128;
    const int z    = blockIdx.z;
    const int wm   = (MODE == 2) ? (wid & 3) * 32 : (wid & 1) * 64;
    const int wn   = (MODE == 2) ? (wid >> 2) * 32 : (wid >> 1) * 32;

    const __nv_bfloat16 *Ah, *Al, *Bh, *Bl;
    int lda, ldb;
    if (MODE == 0) {
        Ah = g_xh + (size_t)bm * C_;  Al = g_xl + (size_t)bm * C_;  lda = C_;
        Bh = g_wqh + (size_t)bn * C_; Bl = g_wql + (size_t)bn * C_; ldb = C_;
    } else if (MODE == 1) {
        size_t ao = (size_t)z * N_ * D_ + (size_t)bm * D_;
        size_t bo = (size_t)z * N_ * D_ + (size_t)bn * D_;
        Ah = g_qh + ao; Al = g_ql + ao; lda = D_;
        Bh = g_kh + bo; Bl = g_kl + bo; ldb = D_;
    } else if (MODE == 2) {
        size_t ao = (size_t)z * N_ * N_ + (size_t)bm * N_;
        size_t bo = (size_t)z * D_ * N_;
        Ah = g_ah + ao;  Al = g_al + ao;  lda = N_;
        Bh = g_vTh + bo; Bl = g_vTl + bo; ldb = N_;
    } else {
        Ah = g_ch + (size_t)bm * C_;  Al = g_cl + (size_t)bm * C_;  lda = C_;
        Bh = g_wph + (size_t)bn * C_; Bl = g_wpl + (size_t)bn * C_; ldb = C_;
    }

    float acc[MA][NA][4];
    #pragma unroll
    for (int i = 0; i < MA; i++)
        #pragma unroll
        for (int j = 0; j < NA; j++)
            #pragma unroll
            for (int r = 0; r < 4; r++) acc[i][j][r] = 0.0f;

    auto issue_loads = [&](int ck) {
        const int b = ck & 1;
        const int kofs = ck * 32;
        const u32 base = sb + b * STAGE;
        #pragma unroll
        for (int i = tid; i < 128 * 4; i += 256) {
            int r = i >> 2, s = i & 3;
            u32 off = (u32)(r * 80 + s * 16);
            CP16(base + off,         Ah + (size_t)r * lda + kofs + s * 8);
            CP16(base + APART + off, Al + (size_t)r * lda + kofs + s * 8);
        }
        #pragma unroll
        for (int i = tid; i < NTILE * 4; i += 256) {
            int r = i >> 2, s = i & 3;
            u32 off = (u32)(r * 80 + s * 16);
            CP16(base + 2 * APART + off,         Bh + (size_t)r * ldb + kofs + s * 8);
            CP16(base + 2 * APART + BPART + off, Bl + (size_t)r * ldb + kofs + s * 8);
        }
        CP_COMMIT();
    };

    auto do_compute = [&](int b) {
        char* cbuf = smem + b * STAGE;
        #pragma unroll
        for (int ks = 0; ks < 2; ks++) {
            const int kb = ks * 32 + t * 4;   // byte offset within 80B row
            u32 a_hi[MA][4], a_lo[MA][4], b_hi[NA][2], b_lo[NA][2];
            #pragma unroll
            for (int ma = 0; ma < MA; ma++) {
                const char* rp = cbuf + (wm + ma * 16 + g) * 80 + kb;
                a_hi[ma][0] = *(const u32*)(rp);
                a_hi[ma][1] = *(const u32*)(rp + 8 * 80);
                a_hi[ma][2] = *(const u32*)(rp + 16);
                a_hi[ma][3] = *(const u32*)(rp + 8 * 80 + 16);
                a_lo[ma][0] = *(const u32*)(rp + APART);
                a_lo[ma][1] = *(const u32*)(rp + APART + 8 * 80);
                a_lo[ma][2] = *(const u32*)(rp + APART + 16);
                a_lo[ma][3] = *(const u32*)(rp + APART + 8 * 80 + 16);
            }
            #pragma unroll
            for (int na = 0; na < NA; na++) {
                const char* rp = cbuf + 2 * APART + (wn + na * 8 + g) * 80 + kb;
                b_hi[na][0] = *(const u32*)(rp);
                b_hi[na][1] = *(const u32*)(rp + 16);
                b_lo[na][0] = *(const u32*)(rp + BPART);
                b_lo[na][1] = *(const u32*)(rp + BPART + 16);
            }
            #pragma unroll
            for (int ma = 0; ma < MA; ma++)
                #pragma unroll
                for (int na = 0; na < NA; na++) {
                    mma16816(acc[ma][na], a_hi[ma], b_hi[na]);
                    mma16816(acc[ma][na], a_hi[ma], b_lo[na]);
                    mma16816(acc[ma][na], a_lo[ma], b_hi[na]);
                }
        }
    };

    issue_loads(0);
    for (int ck = 0; ck < NC; ck++) {
        if (ck + 1 < NC) { issue_loads(ck + 1); CP_WAIT(1); }
        else             { CP_WAIT(0); }
        __syncthreads();
        do_compute(ck & 1);
        __syncthreads();
    }

    // ---- epilogue (register fragments -> per-MODE destinations) ----
    #pragma unroll
    for (int ma = 0; ma < MA; ma++)
        #pragma unroll
        for (int na = 0; na < NA; na++)
            #pragma unroll
            for (int half = 0; half < 2; half++) {
                const int row = bm + wm + ma * 16 + g + half * 8;
                const int col = bn + wn + na * 8 + t * 2;
                float v0 = acc[ma][na][half * 2 + 0];
                float v1 = acc[ma][na][half * 2 + 1];

                if (MODE == 1) {
                    float* dst = out_f32 + (size_t)z * N_ * N_ + (size_t)row * N_ + col;
                    *(float2*)dst = make_float2(v0, v1);
                } else if (MODE == 3) {
                    float* dst = out_f32 + (size_t)row * C_ + col;
                    *(float2*)dst = make_float2(v0 + bias[col], v1 + bias[col + 1]);
                } else if (MODE == 2) {
                    const int b8 = z >> 4, h = z & 15;
                    const size_t base = ((size_t)(b8 * N_ + row)) * C_ + h * 64 + col;
                    __nv_bfloat16 h0, l0, h1, l1;
                    splitf(v0, h0, l0); splitf(v1, h1, l1);
                    *(__nv_bfloat162*)(g_ch + base) = __nv_bfloat162(h0, h1);
                    *(__nv_bfloat162*)(g_cl + base) = __nv_bfloat162(l0, l1);
                } else {  // MODE 0
                    const int which = col >> 10;
                    const int c     = col & 1023;
                    const int h     = c >> 6;
                    const int d0    = c & 63;
                    const int b8    = row >> 10;
                    const int n     = row & 1023;
                    const int bh    = b8 * H_ + h;
                    if (which == 0) {
                        __nv_bfloat16 h0, l0, h1, l1;
                        splitf(v0 * 0.125f, h0, l0); splitf(v1 * 0.125f, h1, l1);
                        const size_t base = ((size_t)bh * N_ + n) * D_ + d0;
                        *(__nv_bfloat162*)(g_qh + base) = __nv_bfloat162(h0, h1);
                        *(__nv_bfloat162*)(g_ql + base) = __nv_bfloat162(l0, l1);
                    } else if (which == 1) {
                        __nv_bfloat16 h0, l0, h1, l1;
                        splitf(v0, h0, l0); splitf(v1, h1, l1);
                        const size_t base = ((size_t)bh * N_ + n) * D_ + d0;
                        *(__nv_bfloat162*)(g_kh + base) = __nv_bfloat162(h0, h1);
                        *(__nv_bfloat162*)(g_kl + base) = __nv_bfloat162(l0, l1);
                    } else {
                        __nv_bfloat16 h0, l0, h1, l1;
                        splitf(v0, h0, l0); splitf(v1, h1, l1);
                        const size_t vb = (size_t)bh * D_ * N_ + n;
                        g_vTh[vb + (size_t)d0 * N_]       = h0;
                        g_vTh[vb + (size_t)(d0 + 1) * N_] = h1;
                        g_vTl[vb + (size_t)d0 * N_]       = l0;
                        g_vTl[vb + (size_t)(d0 + 1) * N_] = l1;
                    }
                }
            }
}

// ---------------- conversion kernels ----------------
__global__ void __launch_bounds__(256) conv_x(const float* __restrict__ s)
{
    int i = blockIdx.x * 256 + threadIdx.x;          // over n4 = M*C/4
    float4 v = ((const float4*)s)[i];
    __nv_bfloat16 h0, l0, h1, l1, h2, l2, h3, l3;
    splitf(v.x, h0, l0); splitf(v.y, h1, l1);
    splitf(v.z, h2, l2); splitf(v.w, h3, l3);
    __nv_bfloat162* hp = (__nv_bfloat162*)g_xh;
    __nv_bfloat162* lp = (__nv_bfloat162*)g_xl;
    hp[i * 2]     = __nv_bfloat162(h0, h1);
    hp[i * 2 + 1] = __nv_bfloat162(h2, h3);
    lp[i * 2]     = __nv_bfloat162(l0, l1);
    lp[i * 2 + 1] = __nv_bfloat162(l2, l3);
}

// transpose + split: src [R, Cc] -> dst [Cc, R];  W=0: w_qkv, W=1: w_proj
template <int W>
__global__ void __launch_bounds__(256) conv_wT(const float* __restrict__ s)
{
    constexpr int R  = C_;
    constexpr int Cc = (W == 0) ? QKVC : C_;
    __nv_bfloat16* dh = (W == 0) ? g_wqh : g_wph;
    __nv_bfloat16* dl = (W == 0) ? g_wql : g_wpl;

    __shared__ float tbuf[32][33];
    const int tx = threadIdx.x & 31, ty = threadIdx.x >> 5;
    const int c0 = blockIdx.x * 32, r0 = blockIdx.y * 32;
    #pragma unroll
    for (int j = 0; j < 4; j++)
        tbuf[ty + j * 8][tx] = s[(size_t)(r0 + ty + j * 8) * Cc + c0 + tx];
    __syncthreads();
    #pragma unroll
    for (int j = 0; j < 4; j++) {
        int i = ty + j * 8;
        float v = tbuf[tx][i];
        __nv_bfloat16 hh, ll;
        splitf(v, hh, ll);
        size_t idx = (size_t)(c0 + i) * R + r0 + tx;
        dh[idx] = hh;
        dl[idx] = ll;
    }
}

// ---------------- softmax (in-place fp32) + split to g_ah/g_al ----------------
__global__ void __launch_bounds__(256) softmax_k(float* __restrict__ a)
{
    __shared__ float smax[8], ssum[8];
    const size_t base = (size_t)blockIdx.x * N_;
    const int t = threadIdx.x, lane = t & 31, w = t >> 5;

    float4 v = ((const float4*)(a + base))[t];
    float m = fmaxf(fmaxf(v.x, v.y), fmaxf(v.z, v.w));
    #pragma unroll
    for (int o = 16; o > 0; o >>= 1) m = fmaxf(m, __shfl_xor_sync(0xffffffffu, m, o));
    if (lane == 0) smax[w] = m;
    __syncthreads();
    if (w == 0) {
        float tm = (lane < 8) ? smax[lane] : -1e30f;
        #pragma unroll
        for (int o = 4; o > 0; o >>= 1) tm = fmaxf(tm, __shfl_xor_sync(0xffffffffu, tm, o));
        if (lane == 0) smax[0] = tm;
    }
    __syncthreads();
    m = smax[0];

    float e0 = __expf(v.x - m), e1 = __expf(v.y - m);
    float e2 = __expf(v.z - m), e3 = __expf(v.w - m);
    float s = e0 + e1 + e2 + e3;
    #pragma unroll
    for (int o = 16; o > 0; o >>= 1) s += __shfl_xor_sync(0xffffffffu, s, o);
    if (lane == 0) ssum[w] = s;
    __syncthreads();
    if (w == 0) {
        float ts = (lane < 8) ? ssum[lane] : 0.0f;
        #pragma unroll
        for (int o = 4; o > 0; o >>= 1) ts += __shfl_xor_sync(0xffffffffu, ts, o);
        if (lane == 0) ssum[0] = ts;
    }
    __syncthreads();
    const float inv = 1.0f / ssum[0];

    float4 p = make_float4(e0 * inv, e1 * inv, e2 * inv, e3 * inv);
    ((float4*)(a + base))[t] = p;

    __nv_bfloat16 h0, l0, h1, l1, h2, l2, h3, l3;
    splitf(p.x, h0, l0); splitf(p.y, h1, l1);
    splitf(p.z, h2, l2); splitf(p.w, h3, l3);
    __nv_bfloat162* ah = (__nv_bfloat162*)g_ah;
    __nv_bfloat162* al = (__nv_bfloat162*)g_al;
    const size_t b2 = (size_t)blockIdx.x * (N_ / 2) + t * 2;
    ah[b2]     = __nv_bfloat162(h0, h1);
    ah[b2 + 1] = __nv_bfloat162(h2, h3);
    al[b2]     = __nv_bfloat162(l0, l1);
    al[b2 + 1] = __nv_bfloat162(l2, l3);
}

// ---------------------------------------------------------------------------
extern "C" void kernel_launch(void* const* d_in, const int* in_sizes, int n_in,
                              void* d_out, int out_size)
{
    const float* x      = (const float*)d_in[0];
    const float* w_qkv  = (const float*)d_in[1];
    const float* w_proj = (const float*)d_in[2];
    const float* b_proj = (const float*)d_in[3];
    float* out  = (float*)d_out;
    float* attn = out + (size_t)M_ * C_;

    const int S128 = 2 * (2 * 128 * 80 + 2 * 128 * 80);   // 81920
    const int S64  = 2 * (2 * 128 * 80 + 2 * 64 * 80);    // 61440

    cudaFuncSetAttribute(mma_gemm<0>, cudaFuncAttributeMaxDynamicSharedMemorySize, S128);
    cudaFuncSetAttribute(mma_gemm<1>, cudaFuncAttributeMaxDynamicSharedMemorySize, S128);
    cudaFuncSetAttribute(mma_gemm<2>, cudaFuncAttributeMaxDynamicSharedMemorySize, S64);
    cudaFuncSetAttribute(mma_gemm<3>, cudaFuncAttributeMaxDynamicSharedMemorySize, S128);

    // 1) input conversions (split fp32 -> bf16 hi/lo; weights transposed)
    conv_x<<<M_ * C_ / 1024, 256>>>(x);
    conv_wT<0><<<dim3(QKVC / 32, C_ / 32), 256>>>(w_qkv);
    conv_wT<1><<<dim3(C_ / 32, C_ / 32), 256>>>(w_proj);

    // 2) QKV GEMM -> q(scaled)/k/vT splits
    mma_gemm<0><<<dim3(QKVC / 128, M_ / 128), 256, S128>>>(nullptr, nullptr);

    // 3) S = q @ k^T (pre-softmax scores, fp32) into attn region
    mma_gemm<1><<<dim3(N_ / 128, N_ / 128, BH_), 256, S128>>>(attn, nullptr);

    // 4) softmax in-place + split to bf16
    softmax_k<<<BH_ * N_, 256>>>(attn);

    // 5) ctx = attn @ V
    mma_gemm<2><<<dim3(1, N_ / 128, BH_), 256, S64>>>(nullptr, nullptr);

    // 6) out = ctx @ w_proj + bias
    mma_gemm<3><<<dim3(C_ / 128, M_ / 128), 256, S128>>>(out, b_proj);
}

// round 4
// speedup vs baseline: 2.6609x; 1.0949x over previous
#include <cuda_runtime.h>
#include <cuda_bf16.h>

typedef unsigned int u32;

#define B_   8
#define N_   1024
#define C_   1024
#define H_   16
#define D_   64
#define M_   (B_ * N_)     // 8192
#define QKVC 3072
#define BH_  (B_ * H_)     // 128

// ---------------- allocation-free scratch (device globals) ----------------
__device__ __align__(256) __nv_bfloat16 g_xh[(size_t)M_ * C_],  g_xl[(size_t)M_ * C_];
__device__ __align__(256) __nv_bfloat16 g_wqh[(size_t)QKVC * C_], g_wql[(size_t)QKVC * C_];
__device__ __align__(256) __nv_bfloat16 g_wph[(size_t)C_ * C_],  g_wpl[(size_t)C_ * C_];
__device__ __align__(256) __nv_bfloat16 g_qh[(size_t)BH_ * N_ * D_], g_ql[(size_t)BH_ * N_ * D_];
__device__ __align__(256) __nv_bfloat16 g_kh[(size_t)BH_ * N_ * D_], g_kl[(size_t)BH_ * N_ * D_];
__device__ __align__(256) __nv_bfloat16 g_vTh[(size_t)BH_ * D_ * N_], g_vTl[(size_t)BH_ * D_ * N_];
__device__ __align__(256) __nv_bfloat16 g_ah[(size_t)BH_ * N_ * N_], g_al[(size_t)BH_ * N_ * N_];
__device__ __align__(256) __nv_bfloat16 g_ch[(size_t)M_ * C_],  g_cl[(size_t)M_ * C_];

// ---------------- helpers ----------------
__device__ __forceinline__ u32 smem_u32(const void* p) {
    u32 a;
    asm("{ .reg .u64 t; cvta.to.shared.u64 t, %1; cvt.u32.u64 %0, t; }" : "=r"(a) : "l"(p));
    return a;
}
#define CP16(dst, src) \
    asm volatile("cp.async.cg.shared.global [%0], [%1], 16;" :: "r"(dst), "l"(src) : "memory")
#define CP_COMMIT() asm volatile("cp.async.commit_group;" ::: "memory")
#define CP_WAIT(n)  asm volatile("cp.async.wait_group %0;" :: "n"(n) : "memory")

__device__ __forceinline__ void ldm4(u32& r0, u32& r1, u32& r2, u32& r3, u32 a) {
    asm volatile("ldmatrix.sync.aligned.m8n8.x4.shared.b16 {%0,%1,%2,%3}, [%4];"
        : "=r"(r0), "=r"(r1), "=r"(r2), "=r"(r3) : "r"(a));
}
__device__ __forceinline__ void mma16816(float* c, const u32* a, const u32* b) {
    asm volatile(
        "mma.sync.aligned.m16n8k16.row.col.f32.bf16.bf16.f32 "
        "{%0,%1,%2,%3}, {%4,%5,%6,%7}, {%8,%9}, {%0,%1,%2,%3};"
        : "+f"(c[0]), "+f"(c[1]), "+f"(c[2]), "+f"(c[3])
        : "r"(a[0]), "r"(a[1]), "r"(a[2]), "r"(a[3]), "r"(b[0]), "r"(b[1]));
}
__device__ __forceinline__ void splitf(float v, __nv_bfloat16& h, __nv_bfloat16& l) {
    h = __float2bfloat16(v);
    l = __float2bfloat16(v - __bfloat162float(h));
}

// ---------------------------------------------------------------------------
// Split-bf16 HMMA GEMM, ldmatrix fragments, 3-stage cp.async ring.
// MODE 0: QKV (x * wqkvT)     -> scatter q(scaled)/k/vT hi+lo
// MODE 2: AV  (attn * vT, bh) -> ctx hi+lo (NTILE=64)
// MODE 3: OUT (ctx * wprojT)  -> fp32 out + bias
// ---------------------------------------------------------------------------
template <int MODE>
__global__ void __launch_bounds__(256, 1) mma_gemm(float* __restrict__ out_f32,
                                                   const float* __restrict__ bias)
{
    constexpr int NTILE = (MODE == 2) ? 64 : 128;
    constexpr int NC    = 32;                    // K = 1024, chunk 32
    constexpr int MA    = (MODE == 2) ? 2 : 4;
    constexpr int NA    = 4;
    constexpr int APART = 128 * 80;
    constexpr int BPART = NTILE * 80;
    constexpr int STAGE = 2 * APART + 2 * BPART;

    extern __shared__ char smem[];
    const u32 sb   = smem_u32(smem);
    const int tid  = threadIdx.x;
    const int wid  = tid >> 5, lane = tid & 31;
    const int g    = lane >> 2, t = lane & 3;
    const int bn   = blockIdx.x * NTILE;
    const int bm   = blockIdx.y * 128;
    const int z    = blockIdx.z;
    const int wm   = (MODE == 2) ? (wid & 3) * 32 : (wid & 1) * 64;
    const int wn   = (MODE == 2) ? (wid >> 2) * 32 : (wid >> 1) * 32;

    const __nv_bfloat16 *Ah, *Al, *Bh, *Bl;
    int lda, ldb;
    if (MODE == 0) {
        Ah = g_xh + (size_t)bm * C_;  Al = g_xl + (size_t)bm * C_;  lda = C_;
        Bh = g_wqh + (size_t)bn * C_; Bl = g_wql + (size_t)bn * C_; ldb = C_;
    } else if (MODE == 2) {
        size_t ao = (size_t)z * N_ * N_ + (size_t)bm * N_;
        size_t bo = (size_t)z * D_ * N_;
        Ah = g_ah + ao;  Al = g_al + ao;  lda = N_;
        Bh = g_vTh + bo; Bl = g_vTl + bo; ldb = N_;
    } else {
        Ah = g_ch + (size_t)bm * C_;  Al = g_cl + (size_t)bm * C_;  lda = C_;
        Bh = g_wph + (size_t)bn * C_; Bl = g_wpl + (size_t)bn * C_; ldb = C_;
    }

    float acc[MA][NA][4];
    #pragma unroll
    for (int i = 0; i < MA; i++)
        #pragma unroll
        for (int j = 0; j < NA; j++)
            #pragma unroll
            for (int r = 0; r < 4; r++) acc[i][j][r] = 0.0f;

    auto issue_loads = [&](int ck, int s) {
        const int kofs = ck * 32;
        const u32 base = sb + s * STAGE;
        #pragma unroll
        for (int i = tid; i < 128 * 4; i += 256) {
            int r = i >> 2, sgm = i & 3;
            u32 off = (u32)(r * 80 + sgm * 16);
            CP16(base + off,         Ah + (size_t)r * lda + kofs + sgm * 8);
            CP16(base + APART + off, Al + (size_t)r * lda + kofs + sgm * 8);
        }
        #pragma unroll
        for (int i = tid; i < NTILE * 4; i += 256) {
            int r = i >> 2, sgm = i & 3;
            u32 off = (u32)(r * 80 + sgm * 16);
            CP16(base + 2 * APART + off,         Bh + (size_t)r * ldb + kofs + sgm * 8);
            CP16(base + 2 * APART + BPART + off, Bl + (size_t)r * ldb + kofs + sgm * 8);
        }
        CP_COMMIT();
    };

    const u32 arow = (u32)((wm + (lane & 15)) * 80 + ((lane >> 4) << 4));
    const u32 brow = (u32)((wn + (lane & 7) + ((lane >> 4) << 3)) * 80 + (((lane >> 3) & 1) << 4));

    auto do_compute = [&](int s) {
        const u32 abase = sb + s * STAGE;
        const u32 bbase = abase + 2 * APART;
        #pragma unroll
        for (int ks = 0; ks < 2; ks++) {
            const u32 kb = ks * 32;
            u32 a_hi[MA][4], a_lo[MA][4], b_hi[NA][2], b_lo[NA][2];
            #pragma unroll
            for (int ma = 0; ma < MA; ma++) {
                u32 ad = abase + arow + ma * 16 * 80 + kb;
                ldm4(a_hi[ma][0], a_hi[ma][1], a_hi[ma][2], a_hi[ma][3], ad);
                ldm4(a_lo[ma][0], a_lo[ma][1], a_lo[ma][2], a_lo[ma][3], ad + APART);
            }
            #pragma unroll
            for (int p = 0; p < NA / 2; p++) {
                u32 bd = bbase + brow + p * 16 * 80 + kb;
                ldm4(b_hi[2*p][0], b_hi[2*p][1], b_hi[2*p+1][0], b_hi[2*p+1][1], bd);
                ldm4(b_lo[2*p][0], b_lo[2*p][1], b_lo[2*p+1][0], b_lo[2*p+1][1], bd + BPART);
            }
            #pragma unroll
            for (int ma = 0; ma < MA; ma++)
                #pragma unroll
                for (int na = 0; na < NA; na++) {
                    mma16816(acc[ma][na], a_hi[ma], b_hi[na]);
                    mma16816(acc[ma][na], a_hi[ma], b_lo[na]);
                    mma16816(acc[ma][na], a_lo[ma], b_hi[na]);
                }
        }
    };

    issue_loads(0, 0);
    issue_loads(1, 1);
    for (int ck = 0; ck < NC; ck++) {
        const int s = ck % 3;
        if (ck + 2 < NC) { issue_loads(ck + 2, (ck + 2) % 3); CP_WAIT(2); }
        else if (ck + 1 < NC) { CP_WAIT(1); }
        else { CP_WAIT(0); }
        __syncthreads();
        do_compute(s);
        __syncthreads();
    }

    // ---- epilogue ----
    #pragma unroll
    for (int ma = 0; ma < MA; ma++)
        #pragma unroll
        for (int na = 0; na < NA; na++)
            #pragma unroll
            for (int half = 0; half < 2; half++) {
                const int row = bm + wm + ma * 16 + g + half * 8;
                const int col = bn + wn + na * 8 + t * 2;
                float v0 = acc[ma][na][half * 2 + 0];
                float v1 = acc[ma][na][half * 2 + 1];

                if (MODE == 3) {
                    float* dst = out_f32 + (size_t)row * C_ + col;
                    *(float2*)dst = make_float2(v0 + bias[col], v1 + bias[col + 1]);
                } else if (MODE == 2) {
                    const int b8 = z >> 4, h = z & 15;
                    const size_t base = ((size_t)(b8 * N_ + row)) * C_ + h * 64 + col;
                    __nv_bfloat16 h0, l0, h1, l1;
                    splitf(v0, h0, l0); splitf(v1, h1, l1);
                    *(__nv_bfloat162*)(g_ch + base) = __nv_bfloat162(h0, h1);
                    *(__nv_bfloat162*)(g_cl + base) = __nv_bfloat162(l0, l1);
                } else {  // MODE 0
                    const int which = col >> 10;
                    const int c     = col & 1023;
                    const int h     = c >> 6;
                    const int d0    = c & 63;
                    const int b8    = row >> 10;
                    const int n     = row & 1023;
                    const int bh    = b8 * H_ + h;
                    if (which == 0) {
                        __nv_bfloat16 h0, l0, h1, l1;
                        splitf(v0 * 0.125f, h0, l0); splitf(v1 * 0.125f, h1, l1);
                        const size_t base = ((size_t)bh * N_ + n) * D_ + d0;
                        *(__nv_bfloat162*)(g_qh + base) = __nv_bfloat162(h0, h1);
                        *(__nv_bfloat162*)(g_ql + base) = __nv_bfloat162(l0, l1);
                    } else if (which == 1) {
                        __nv_bfloat16 h0, l0, h1, l1;
                        splitf(v0, h0, l0); splitf(v1, h1, l1);
                        const size_t base = ((size_t)bh * N_ + n) * D_ + d0;
                        *(__nv_bfloat162*)(g_kh + base) = __nv_bfloat162(h0, h1);
                        *(__nv_bfloat162*)(g_kl + base) = __nv_bfloat162(l0, l1);
                    } else {
                        __nv_bfloat16 h0, l0, h1, l1;
                        splitf(v0, h0, l0); splitf(v1, h1, l1);
                        const size_t vb = (size_t)bh * D_ * N_ + n;
                        g_vTh[vb + (size_t)d0 * N_]       = h0;
                        g_vTh[vb + (size_t)(d0 + 1) * N_] = h1;
                        g_vTl[vb + (size_t)d0 * N_]       = l0;
                        g_vTl[vb + (size_t)(d0 + 1) * N_] = l1;
                    }
                }
            }
}

// ---------------------------------------------------------------------------
// Fused S = qk^T -> softmax -> attn fp32 out + bf16 split (per 32-row slab).
// Smem: Qh/Ql (32x144B x2 = 9216), K 2-stage ring (2 x 36864), S (32 x 4144).
// ---------------------------------------------------------------------------
#define Q_OFF  0
#define QL_OFF 4608
#define K_OFF  9216
#define KSTG   36864
#define KL_OFF 18432
#define S_OFF  82944
#define S_PIT  4144
#define SS_SMEM (S_OFF + 32 * S_PIT)   // 215552

__global__ void __launch_bounds__(256, 1) sscore_kernel(float* __restrict__ attn)
{
    extern __shared__ char smem[];
    const u32 sb   = smem_u32(smem);
    const int tid  = threadIdx.x;
    const int wid  = tid >> 5, lane = tid & 31;
    const int g    = lane >> 2, t = lane & 3;

    const int bh   = blockIdx.x >> 5;
    const int row0 = (blockIdx.x & 31) * 32;
    const int wm   = (wid & 1) * 16;
    const int wn   = (wid >> 1) * 32;

    const __nv_bfloat16* Qh = g_qh + ((size_t)bh * N_ + row0) * D_;
    const __nv_bfloat16* Ql = g_ql + ((size_t)bh * N_ + row0) * D_;
    const __nv_bfloat16* Kh = g_kh + (size_t)bh * N_ * D_;
    const __nv_bfloat16* Kl = g_kl + (size_t)bh * N_ * D_;

    // Q slab: 32 rows x 128B, pitch 144
    {
        int r = tid >> 3, sgm = tid & 7;     // 256 = 32*8
        u32 off = (u32)(r * 144 + sgm * 16);
        *(float4*)(smem + Q_OFF + off)  = *(const float4*)(Qh + r * D_ + sgm * 8);
        *(float4*)(smem + QL_OFF + off) = *(const float4*)(Ql + r * D_ + sgm * 8);
    }

    auto issueK = [&](int c, int s) {
        const u32 base = sb + K_OFF + s * KSTG;
        const size_t ko = (size_t)c * 128 * D_;
        #pragma unroll
        for (int i = tid; i < 128 * 8; i += 256) {
            int r = i >> 3, sgm = i & 7;
            u32 off = (u32)(r * 144 + sgm * 16);
            CP16(base + off,          Kh + ko + r * D_ + sgm * 8);
            CP16(base + KL_OFF + off, Kl + ko + r * D_ + sgm * 8);
        }
        CP_COMMIT();
    };

    const u32 arow = (u32)((wm + (lane & 15)) * 144 + ((lane >> 4) << 4));
    const u32 brow = (u32)((wn + (lane & 7) + ((lane >> 4) << 3)) * 144 + (((lane >> 3) & 1) << 4));

    issueK(0, 0);
    issueK(1, 1);
    for (int c = 0; c < 8; c++) {
        if (c < 7) CP_WAIT(1); else CP_WAIT(0);
        __syncthreads();

        const u32 kb0 = sb + K_OFF + (c & 1) * KSTG;
        float acc[4][4];
        #pragma unroll
        for (int j = 0; j < 4; j++)
            #pragma unroll
            for (int r = 0; r < 4; r++) acc[j][r] = 0.0f;

        #pragma unroll
        for (int ks = 0; ks < 4; ks++) {
            const u32 kb = ks * 32;
            u32 a_hi[4], a_lo[4], b_hi[4][2], b_lo[4][2];
            u32 ad = sb + Q_OFF + arow + kb;
            ldm4(a_hi[0], a_hi[1], a_hi[2], a_hi[3], ad);
            ldm4(a_lo[0], a_lo[1], a_lo[2], a_lo[3], ad + QL_OFF);
            #pragma unroll
            for (int p = 0; p < 2; p++) {
                u32 bd = kb0 + brow + p * 16 * 144 + kb;
                ldm4(b_hi[2*p][0], b_hi[2*p][1], b_hi[2*p+1][0], b_hi[2*p+1][1], bd);
                ldm4(b_lo[2*p][0], b_lo[2*p][1], b_lo[2*p+1][0], b_lo[2*p+1][1], bd + KL_OFF);
            }
            #pragma unroll
            for (int na = 0; na < 4; na++) {
                mma16816(acc[na], a_hi, b_hi[na]);
                mma16816(acc[na], a_hi, b_lo[na]);
                mma16816(acc[na], a_lo, b_hi[na]);
            }
        }

        #pragma unroll
        for (int na = 0; na < 4; na++)
            #pragma unroll
            for (int half = 0; half < 2; half++) {
                int row = wm + g + half * 8;
                int col = c * 128 + wn + na * 8 + t * 2;
                *(float2*)(smem + S_OFF + row * S_PIT + col * 4) =
                    make_float2(acc[na][half * 2], acc[na][half * 2 + 1]);
            }

        __syncthreads();
        if (c + 2 < 8) issueK(c + 2, c & 1);
    }

    // ---- softmax over rows (4 rows per warp) + outputs ----
    #pragma unroll
    for (int rr = 0; rr < 4; rr++) {
        const int r = wid * 4 + rr;
        const float* Srow = (const float*)(smem + S_OFF + r * S_PIT);
        float4 f[8];
        float m = -1e30f;
        #pragma unroll
        for (int i = 0; i < 8; i++) {
            f[i] = *(const float4*)(Srow + (lane + i * 32) * 4);
            m = fmaxf(m, fmaxf(fmaxf(f[i].x, f[i].y), fmaxf(f[i].z, f[i].w)));
        }
        #pragma unroll
        for (int o = 16; o > 0; o >>= 1) m = fmaxf(m, __shfl_xor_sync(0xffffffffu, m, o));
        float s = 0.0f;
        #pragma unroll
        for (int i = 0; i < 8; i++) {
            f[i].x = __expf(f[i].x - m); f[i].y = __expf(f[i].y - m);
            f[i].z = __expf(f[i].z - m); f[i].w = __expf(f[i].w - m);
            s += f[i].x + f[i].y + f[i].z + f[i].w;
        }
        #pragma unroll
        for (int o = 16; o > 0; o >>= 1) s += __shfl_xor_sync(0xffffffffu, s, o);
        const float inv = 1.0f / s;

        const size_t gr = (size_t)bh * N_ + row0 + r;
        float* ap = attn + gr * N_;
        __nv_bfloat162* ahp = ((__nv_bfloat162*)g_ah) + gr * (N_ / 2);
        __nv_bfloat162* alp = ((__nv_bfloat162*)g_al) + gr * (N_ / 2);
        #pragma unroll
        for (int i = 0; i < 8; i++) {
            float4 p = make_float4(f[i].x * inv, f[i].y * inv, f[i].z * inv, f[i].w * inv);
            *(float4*)(ap + (lane + i * 32) * 4) = p;
            __nv_bfloat16 h0, l0, h1, l1, h2, l2, h3, l3;
            splitf(p.x, h0, l0); splitf(p.y, h1, l1);
            splitf(p.z, h2, l2); splitf(p.w, h3, l3);
            const int c2 = (lane + i * 32) * 2;
            ahp[c2]     = __nv_bfloat162(h0, h1);
            ahp[c2 + 1] = __nv_bfloat162(h2, h3);
            alp[c2]     = __nv_bfloat162(l0, l1);
            alp[c2 + 1] = __nv_bfloat162(l2, l3);
        }
    }
}

// ---------------- conversion kernels ----------------
__global__ void __launch_bounds__(256) conv_x(const float* __restrict__ s)
{
    int i = blockIdx.x * 256 + threadIdx.x;
    float4 v = ((const float4*)s)[i];
    __nv_bfloat16 h0, l0, h1, l1, h2, l2, h3, l3;
    splitf(v.x, h0, l0); splitf(v.y, h1, l1);
    splitf(v.z, h2, l2); splitf(v.w, h3, l3);
    __nv_bfloat162* hp = (__nv_bfloat162*)g_xh;
    __nv_bfloat162* lp = (__nv_bfloat162*)g_xl;
    hp[i * 2]     = __nv_bfloat162(h0, h1);
    hp[i * 2 + 1] = __nv_bfloat162(h2, h3);
    lp[i * 2]     = __nv_bfloat162(l0, l1);
    lp[i * 2 + 1] = __nv_bfloat162(l2, l3);
}

template <int W>
__global__ void __launch_bounds__(256) conv_wT(const float* __restrict__ s)
{
    constexpr int R  = C_;
    constexpr int Cc = (W == 0) ? QKVC : C_;
    __nv_bfloat16* dh = (W == 0) ? g_wqh : g_wph;
    __nv_bfloat16* dl = (W == 0) ? g_wql : g_wpl;

    __shared__ float tbuf[32][33];
    const int tx = threadIdx.x & 31, ty = threadIdx.x >> 5;
    const int c0 = blockIdx.x * 32, r0 = blockIdx.y * 32;
    #pragma unroll
    for (int j = 0; j < 4; j++)
        tbuf[ty + j * 8][tx] = s[(size_t)(r0 + ty + j * 8) * Cc + c0 + tx];
    __syncthreads();
    #pragma unroll
    for (int j = 0; j < 4; j++) {
        int i = ty + j * 8;
        float v = tbuf[tx][i];
        __nv_bfloat16 hh, ll;
        splitf(v, hh, ll);
        size_t idx = (size_t)(c0 + i) * R + r0 + tx;
        dh[idx] = hh;
        dl[idx] = ll;
    }
}

// ---------------------------------------------------------------------------
extern "C" void kernel_launch(void* const* d_in, const int* in_sizes, int n_in,
                              void* d_out, int out_size)
{
    const float* x      = (const float*)d_in[0];
    const float* w_qkv  = (const float*)d_in[1];
    const float* w_proj = (const float*)d_in[2];
    const float* b_proj = (const float*)d_in[3];
    float* out  = (float*)d_out;
    float* attn = out + (size_t)M_ * C_;

    const int S128 = 3 * (2 * 128 * 80 + 2 * 128 * 80);   // 122880
    const int S64  = 3 * (2 * 128 * 80 + 2 * 64 * 80);    // 92160

    cudaFuncSetAttribute(mma_gemm<0>, cudaFuncAttributeMaxDynamicSharedMemorySize, S128);
    cudaFuncSetAttribute(mma_gemm<2>, cudaFuncAttributeMaxDynamicSharedMemorySize, S64);
    cudaFuncSetAttribute(mma_gemm<3>, cudaFuncAttributeMaxDynamicSharedMemorySize, S128);
    cudaFuncSetAttribute(sscore_kernel, cudaFuncAttributeMaxDynamicSharedMemorySize, SS_SMEM);

    // 1) input conversions
    conv_x<<<M_ * C_ / 1024, 256>>>(x);
    conv_wT<0><<<dim3(QKVC / 32, C_ / 32), 256>>>(w_qkv);
    conv_wT<1><<<dim3(C_ / 32, C_ / 32), 256>>>(w_proj);

    // 2) QKV GEMM -> q(scaled)/k/vT splits
    mma_gemm<0><<<dim3(QKVC / 128, M_ / 128), 256, S128>>>(nullptr, nullptr);

    // 3) fused S + softmax + attn write + bf16 split
    sscore_kernel<<<BH_ * 32, 256, SS_SMEM>>>(attn);

    // 4) ctx = attn @ V
    mma_gemm<2><<<dim3(1, N_ / 128, BH_), 256, S64>>>(nullptr, nullptr);

    // 5) out = ctx @ w_proj + bias
    mma_gemm<3><<<dim3(C_ / 128, M_ / 128), 256, S128>>>(out, b_proj);
}